// round 16
// baseline (speedup 1.0000x reference)
#include <cuda_runtime.h>

#define NPTS 512
#define CDIM 384
#define LDIM 208   // 192 QK + 16 pair
#define NB 8
#define WPAD 448   // padded packed-W width

typedef unsigned long long ull;

// ---------------- device scratch ----------------
__device__ float g_x[NB * NPTS * CDIM];      // folded features
__device__ float g_S0[NB * NPTS * NPTS];     // qk result (pre-epilogue)
__device__ float g_L[NB * NPTS * LDIM];      // [Q*HS | ap*relu(x@Wpi+bpi)]
__device__ float g_R[NB * NPTS * LDIM];      // [K    | relu(x@Wpj+bpj)   ]
__device__ float g_d[NB * NPTS];             // x@Wd + bd
__device__ float g_rot[2 * NB];              // (cos t0, sin t0) per batch
__device__ float g_W[CDIM * WPAD];           // packed+padded [Wq|Wk|Wpi|Wpj|Wd|0]

// ---------------- f32x2 helpers ----------------
__device__ __forceinline__ ull pack2(float lo, float hi) {
    ull r; asm("mov.b64 %0,{%1,%2};" : "=l"(r) : "f"(lo), "f"(hi)); return r;
}
__device__ __forceinline__ void unpack2(ull v, float& lo, float& hi) {
    asm("mov.b64 {%0,%1},%2;" : "=f"(lo), "=f"(hi) : "l"(v));
}
__device__ __forceinline__ ull fma2(ull a, ull b, ull c) {
    ull d; asm("fma.rn.f32x2 %0,%1,%2,%3;" : "=l"(d) : "l"(a), "l"(b), "l"(c)); return d;
}

// ---------------- tf32 mma helpers ----------------
__device__ __forceinline__ float f2tf32(float x) {
    unsigned u; asm("cvt.rna.tf32.f32 %0,%1;" : "=r"(u) : "f"(x));
    return __uint_as_float(u);
}
__device__ __forceinline__ void mma_tf32(float& c0, float& c1, float& c2, float& c3,
                                         unsigned a0, unsigned a1, unsigned a2, unsigned a3,
                                         unsigned b0, unsigned b1) {
    asm("mma.sync.aligned.m16n8k8.row.col.f32.tf32.tf32.f32 "
        "{%0,%1,%2,%3},{%4,%5,%6,%7},{%8,%9},{%0,%1,%2,%3};"
        : "+f"(c0), "+f"(c1), "+f"(c2), "+f"(c3)
        : "r"(a0), "r"(a1), "r"(a2), "r"(a3), "r"(b0), "r"(b1));
}

// ---------------- threefry / jax normal ----------------
__device__ __forceinline__ unsigned rotl32(unsigned v, int s) {
    return (v << s) | (v >> (32 - s));
}

__device__ void threefry2x32(unsigned k0, unsigned k1, unsigned c0, unsigned c1,
                             unsigned& o0, unsigned& o1) {
    unsigned k2 = k0 ^ k1 ^ 0x1BD11BDAu;
    unsigned x0 = c0 + k0, x1 = c1 + k1;
#define TF_R(r) { x0 += x1; x1 = rotl32(x1, r); x1 ^= x0; }
    TF_R(13) TF_R(15) TF_R(26) TF_R(6)   x0 += k1; x1 += k2 + 1u;
    TF_R(17) TF_R(29) TF_R(16) TF_R(24)  x0 += k2; x1 += k0 + 2u;
    TF_R(13) TF_R(15) TF_R(26) TF_R(6)   x0 += k0; x1 += k1 + 3u;
    TF_R(17) TF_R(29) TF_R(16) TF_R(24)  x0 += k1; x1 += k2 + 4u;
    TF_R(13) TF_R(15) TF_R(26) TF_R(6)   x0 += k2; x1 += k0 + 5u;
#undef TF_R
    o0 = x0; o1 = x1;
}

__device__ unsigned jax_random_bits_partitionable(unsigned i) {
    unsigned o0, o1;
    threefry2x32(0u, 42u, 0u, i, o0, o1);
    return o0 ^ o1;
}

__device__ float erfinv_f(float x) {
    float w = -log1pf(-x * x);
    float p;
    if (w < 5.0f) {
        w -= 2.5f;
        p = 2.81022636e-08f;
        p = fmaf(p, w, 3.43273939e-07f);
        p = fmaf(p, w, -3.5233877e-06f);
        p = fmaf(p, w, -4.39150654e-06f);
        p = fmaf(p, w, 0.00021858087f);
        p = fmaf(p, w, -0.00125372503f);
        p = fmaf(p, w, -0.00417768164f);
        p = fmaf(p, w, 0.246640727f);
        p = fmaf(p, w, 1.50140941f);
    } else {
        w = sqrtf(w) - 3.0f;
        p = -0.000200214257f;
        p = fmaf(p, w, 0.000100950558f);
        p = fmaf(p, w, 0.00134934322f);
        p = fmaf(p, w, -0.00367342844f);
        p = fmaf(p, w, 0.00573950773f);
        p = fmaf(p, w, -0.0076224613f);
        p = fmaf(p, w, 0.00943887047f);
        p = fmaf(p, w, 1.00167406f);
        p = fmaf(p, w, 2.83297682f);
    }
    return p * x;
}

__device__ float jax_normal_from_bits(unsigned bits) {
    float f = __uint_as_float((bits >> 9) | 0x3f800000u) - 1.0f;  // [0,1)
    float lo = __uint_as_float(0xBF7FFFFFu);                      // nextafter(-1,0)
    float span = 1.0f - lo;
    float val = f * span + lo;
    val = fmaxf(lo, val);
    return 1.41421356237f * erfinv_f(val);
}

// ---------------- theta0 ----------------
__global__ void theta0_kernel(const float* __restrict__ xy) {
    int w = threadIdx.x >> 5, lane = threadIdx.x & 31;
    const float* p = xy + (size_t)w * NPTS * 2;
    float sx = 0.f, sy = 0.f;
    for (int i = lane; i < NPTS; i += 32) { sx += p[2 * i]; sy += p[2 * i + 1]; }
    for (int o = 16; o; o >>= 1) {
        sx += __shfl_xor_sync(~0u, sx, o);
        sy += __shfl_xor_sync(~0u, sy, o);
    }
    float mx = sx / (float)NPTS, my = sy / (float)NPTS;
    float cxx = 0.f, cxy = 0.f, cyy = 0.f;
    for (int i = lane; i < NPTS; i += 32) {
        float a = p[2 * i] - mx, b = p[2 * i + 1] - my;
        cxx += a * a; cxy += a * b; cyy += b * b;
    }
    for (int o = 16; o; o >>= 1) {
        cxx += __shfl_xor_sync(~0u, cxx, o);
        cxy += __shfl_xor_sync(~0u, cxy, o);
        cyy += __shfl_xor_sync(~0u, cyy, o);
    }
    if (lane == 0) {
        float denom = (float)NPTS + 1e-8f;
        cxx /= denom; cxy /= denom; cyy /= denom;
        unsigned n0bits = jax_random_bits_partitionable(2u * (unsigned)w);
        unsigned n1bits = jax_random_bits_partitionable(2u * (unsigned)w + 1u);
        float v0 = jax_normal_from_bits(n0bits);
        float v1 = jax_normal_from_bits(n1bits);
        float nrm = sqrtf(v0 * v0 + v1 * v1);
        v0 /= (nrm + 1e-8f); v1 /= (nrm + 1e-8f);
#pragma unroll
        for (int it = 0; it < 5; ++it) {
            float w0 = cxx * v0 + cxy * v1;
            float w1 = cxy * v0 + cyy * v1;
            nrm = sqrtf(w0 * w0 + w1 * w1);
            v0 = w0 / (nrm + 1e-8f);
            v1 = w1 / (nrm + 1e-8f);
        }
        g_rot[2 * w] = v0;
        g_rot[2 * w + 1] = v1;
    }
}

// ---------------- fold feats -> g_x ----------------
__global__ void fold_kernel(const float* __restrict__ feats) {
    int idx = blockIdx.x * 256 + threadIdx.x;
    if (idx >= NB * NPTS * (CDIM / 4)) return;
    int c4 = idx % (CDIM / 4);
    int pn = idx / (CDIM / 4);
    int b = pn >> 9, n = pn & 511;
    const float* base = feats + ((size_t)b * (2 * NPTS + 1) + 1 + 2 * n) * CDIM + c4 * 4;
    float4 u = *(const float4*)base;
    float4 v = *(const float4*)(base + CDIM);
    float4 o = make_float4(0.5f * (u.x + v.x), 0.5f * (u.y + v.y),
                           0.5f * (u.z + v.z), 0.5f * (u.w + v.w));
    *(float4*)&g_x[(size_t)pn * CDIM + c4 * 4] = o;
}

// ---------------- pack projection weights ----------------
__global__ void pack_w_kernel(const float* __restrict__ Wq, const float* __restrict__ Wk,
                              const float* __restrict__ Wpi, const float* __restrict__ Wpj,
                              const float* __restrict__ Wd) {
    int idx = blockIdx.x * 256 + threadIdx.x;
    if (idx >= CDIM * WPAD) return;
    int k = idx / WPAD, j = idx - k * WPAD;
    float w;
    if (j < 192)       w = Wq[k * 192 + j];
    else if (j < 384)  w = Wk[k * 192 + j - 192];
    else if (j < 400)  w = Wpi[k * 16 + j - 384];
    else if (j < 416)  w = Wpj[k * 16 + j - 400];
    else if (j == 416) w = Wd[k];
    else               w = 0.f;
    g_W[idx] = w;
}

// ---------------- proj GEMM tf32 mma: 128(pts) x 64(cols), 256 thr, dbuf ----------------
__global__ __launch_bounds__(256) void proj_mma_kernel(
    const float* __restrict__ bpi, const float* __restrict__ bpj,
    const float* __restrict__ alpha_pair, const float* __restrict__ bd) {
    __shared__ float As[2][128][20];
    __shared__ float Bs[2][64][20];
    int tid = threadIdx.x;
    int m0 = blockIdx.x * 128;     // point rows
    int n0c = blockIdx.y * 64;     // W cols
    int w = tid >> 5, lane = tid & 31;
    int wn = w >> 1, wm = w & 1;   // 4x2 warp grid: 32 rows x 32 cols each
    int g = lane >> 2, tc4 = lane & 3;

    float acc[2][4][4];
#pragma unroll
    for (int i = 0; i < 2; i++)
#pragma unroll
        for (int j = 0; j < 4; j++)
#pragma unroll
            for (int q = 0; q < 4; q++) acc[i][j][q] = 0.f;

    int frow = tid >> 1, fq = tid & 1;         // A fill: 128 rows, 8 floats each
    const float* xrow = g_x + (size_t)(m0 + frow) * CDIM;
    int wk = tid >> 4, wc4 = (tid & 15) * 4;   // B fill: 16 k x 16 col-quads

#define PROJ_LOAD(buf, kc) { \
        float4 u0 = *(const float4*)&xrow[(kc) + fq * 8]; \
        float4 u1 = *(const float4*)&xrow[(kc) + fq * 8 + 4]; \
        As[buf][frow][fq * 8 + 0] = f2tf32(u0.x); As[buf][frow][fq * 8 + 1] = f2tf32(u0.y); \
        As[buf][frow][fq * 8 + 2] = f2tf32(u0.z); As[buf][frow][fq * 8 + 3] = f2tf32(u0.w); \
        As[buf][frow][fq * 8 + 4] = f2tf32(u1.x); As[buf][frow][fq * 8 + 5] = f2tf32(u1.y); \
        As[buf][frow][fq * 8 + 6] = f2tf32(u1.z); As[buf][frow][fq * 8 + 7] = f2tf32(u1.w); \
        float4 w0 = *(const float4*)&g_W[(size_t)((kc) + wk) * WPAD + n0c + wc4]; \
        Bs[buf][wc4 + 0][wk] = f2tf32(w0.x); Bs[buf][wc4 + 1][wk] = f2tf32(w0.y); \
        Bs[buf][wc4 + 2][wk] = f2tf32(w0.z); Bs[buf][wc4 + 3][wk] = f2tf32(w0.w); \
    }

    PROJ_LOAD(0, 0);
    __syncthreads();

    const int NC = CDIM / 16;   // 24
    for (int c = 0; c < NC; ++c) {
        int cur = c & 1;
        if (c + 1 < NC) PROJ_LOAD((c + 1) & 1, (c + 1) * 16);
#pragma unroll
        for (int kk = 0; kk < 16; kk += 8) {
            unsigned a[2][4];
#pragma unroll
            for (int i = 0; i < 2; i++) {
                int an = wn * 32 + i * 16;
                a[i][0] = __float_as_uint(As[cur][an + g][kk + tc4]);
                a[i][1] = __float_as_uint(As[cur][an + g + 8][kk + tc4]);
                a[i][2] = __float_as_uint(As[cur][an + g][kk + tc4 + 4]);
                a[i][3] = __float_as_uint(As[cur][an + g + 8][kk + tc4 + 4]);
            }
            unsigned bb[4][2];
#pragma unroll
            for (int j = 0; j < 4; j++) {
                int bm = wm * 32 + j * 8;
                bb[j][0] = __float_as_uint(Bs[cur][bm + g][kk + tc4]);
                bb[j][1] = __float_as_uint(Bs[cur][bm + g][kk + tc4 + 4]);
            }
#pragma unroll
            for (int i = 0; i < 2; i++)
#pragma unroll
                for (int j = 0; j < 4; j++)
                    mma_tf32(acc[i][j][0], acc[i][j][1], acc[i][j][2], acc[i][j][3],
                             a[i][0], a[i][1], a[i][2], a[i][3], bb[j][0], bb[j][1]);
        }
        __syncthreads();
    }
#undef PROJ_LOAD

    float ap = fmaxf(alpha_pair[0], 0.f);
    float bd0 = bd[0];
    const float HS = 0.17677669529663687f;  // 1/sqrt(32)

#pragma unroll
    for (int i = 0; i < 2; i++) {
#pragma unroll
        for (int j = 0; j < 4; j++) {
#pragma unroll
            for (int q = 0; q < 4; q++) {
                int p = m0 + wn * 32 + i * 16 + g + (q >= 2 ? 8 : 0);
                int col = n0c + wm * 32 + j * 8 + tc4 * 2 + (q & 1);
                float val = acc[i][j][q];
                if (col < 192)       g_L[(size_t)p * LDIM + col] = val * HS;
                else if (col < 384)  g_R[(size_t)p * LDIM + (col - 192)] = val;
                else if (col < 400)  g_L[(size_t)p * LDIM + 192 + (col - 384)] = fmaxf(val + bpi[col - 384], 0.f) * ap;
                else if (col < 416)  g_R[(size_t)p * LDIM + 192 + (col - 400)] = fmaxf(val + bpj[col - 400], 0.f);
                else if (col == 416) g_d[p] = val + bd0;
            }
        }
    }
}

// ---------------- qk GEMM tf32 mma: 64x64 tile, 128 thr, dbuf ----------------
__global__ __launch_bounds__(128) void qk_mma_kernel() {
    __shared__ float Ls[2][64][20];
    __shared__ float Rs[2][64][20];
    int tid = threadIdx.x;
    int b = blockIdx.z;
    int m0 = blockIdx.x * 64;
    int n0 = blockIdx.y * 64;
    int w = tid >> 5, lane = tid & 31;
    int wn = w >> 1, wm = w & 1;
    int g = lane >> 2, tc4 = lane & 3;

    float acc[2][4][4];
#pragma unroll
    for (int i = 0; i < 2; i++)
#pragma unroll
        for (int j = 0; j < 4; j++)
#pragma unroll
            for (int q = 0; q < 4; q++) acc[i][j][q] = 0.f;

    int frow = tid >> 1, fq = tid & 1;
    const float* lrow = g_L + (size_t)(b * NPTS + n0 + frow) * LDIM;
    const float* rrow = g_R + (size_t)(b * NPTS + m0 + frow) * LDIM;

#define QK_LOAD(buf, kc) { \
        float4 u0 = *(const float4*)&lrow[(kc) + fq * 8]; \
        float4 u1 = *(const float4*)&lrow[(kc) + fq * 8 + 4]; \
        Ls[buf][frow][fq * 8 + 0] = f2tf32(u0.x); Ls[buf][frow][fq * 8 + 1] = f2tf32(u0.y); \
        Ls[buf][frow][fq * 8 + 2] = f2tf32(u0.z); Ls[buf][frow][fq * 8 + 3] = f2tf32(u0.w); \
        Ls[buf][frow][fq * 8 + 4] = f2tf32(u1.x); Ls[buf][frow][fq * 8 + 5] = f2tf32(u1.y); \
        Ls[buf][frow][fq * 8 + 6] = f2tf32(u1.z); Ls[buf][frow][fq * 8 + 7] = f2tf32(u1.w); \
        float4 v0 = *(const float4*)&rrow[(kc) + fq * 8]; \
        float4 v1 = *(const float4*)&rrow[(kc) + fq * 8 + 4]; \
        Rs[buf][frow][fq * 8 + 0] = f2tf32(v0.x); Rs[buf][frow][fq * 8 + 1] = f2tf32(v0.y); \
        Rs[buf][frow][fq * 8 + 2] = f2tf32(v0.z); Rs[buf][frow][fq * 8 + 3] = f2tf32(v0.w); \
        Rs[buf][frow][fq * 8 + 4] = f2tf32(v1.x); Rs[buf][frow][fq * 8 + 5] = f2tf32(v1.y); \
        Rs[buf][frow][fq * 8 + 6] = f2tf32(v1.z); Rs[buf][frow][fq * 8 + 7] = f2tf32(v1.w); \
    }

    QK_LOAD(0, 0);
    __syncthreads();

    const int NC = LDIM / 16;   // 13
    for (int c = 0; c < NC; ++c) {
        int cur = c & 1;
        if (c + 1 < NC) QK_LOAD((c + 1) & 1, (c + 1) * 16);
#pragma unroll
        for (int kk = 0; kk < 16; kk += 8) {
            unsigned a[2][4];
#pragma unroll
            for (int i = 0; i < 2; i++) {
                int an = wn * 32 + i * 16;
                a[i][0] = __float_as_uint(Ls[cur][an + g][kk + tc4]);
                a[i][1] = __float_as_uint(Ls[cur][an + g + 8][kk + tc4]);
                a[i][2] = __float_as_uint(Ls[cur][an + g][kk + tc4 + 4]);
                a[i][3] = __float_as_uint(Ls[cur][an + g + 8][kk + tc4 + 4]);
            }
            unsigned bb[4][2];
#pragma unroll
            for (int j = 0; j < 4; j++) {
                int bm = wm * 32 + j * 8;
                bb[j][0] = __float_as_uint(Rs[cur][bm + g][kk + tc4]);
                bb[j][1] = __float_as_uint(Rs[cur][bm + g][kk + tc4 + 4]);
            }
#pragma unroll
            for (int i = 0; i < 2; i++)
#pragma unroll
                for (int j = 0; j < 4; j++)
                    mma_tf32(acc[i][j][0], acc[i][j][1], acc[i][j][2], acc[i][j][3],
                             a[i][0], a[i][1], a[i][2], a[i][3], bb[j][0], bb[j][1]);
        }
        __syncthreads();
    }
#undef QK_LOAD

#pragma unroll
    for (int i = 0; i < 2; i++) {
#pragma unroll
        for (int j = 0; j < 4; j++) {
            int rn = n0 + wn * 32 + i * 16 + g;
            int cm = m0 + wm * 32 + j * 8 + tc4 * 2;
            size_t o0 = ((size_t)b * NPTS + rn) * NPTS + cm;
            size_t o1 = o0 + 8 * NPTS;
            *(float2*)&g_S0[o0] = make_float2(acc[i][j][0], acc[i][j][1]);
            *(float2*)&g_S0[o1] = make_float2(acc[i][j][2], acc[i][j][3]);
        }
    }
}

// ---------------- per-pair MLP epilogue: 128 thr, 16n x 64m, 8 m/thread ----------------
__global__ __launch_bounds__(128) void pair_kernel(
    float* __restrict__ S, const float* __restrict__ xy,
    const float* __restrict__ Wg1, const float* __restrict__ bg1,
    const float* __restrict__ Wg2, const float* __restrict__ bg2,
    const float* __restrict__ alpha_geom,
    const float* __restrict__ Wa1, const float* __restrict__ ba1,
    const float* __restrict__ Wa2, const float* __restrict__ ba2,
    const float* __restrict__ alpha_angle,
    const float* __restrict__ logit_scale) {
    __shared__ ull sWg1d[12 * 32];
    __shared__ ull sbg1d[32];
    __shared__ float sWg2[32];
    __shared__ ull sWa1d[6 * 16];
    __shared__ ull sba1d[16];
    __shared__ float sWa2[16];
    __shared__ float sxn[16], syn[16], sdn[16];
    __shared__ float sxm[64], sym[64];

    int tid = threadIdx.x;
    int b = blockIdx.z;
    int m0 = blockIdx.x * 64;
    int n0 = blockIdx.y * 16;

    for (int i = tid; i < 384; i += 128) { float w = Wg1[i]; sWg1d[i] = pack2(w, w); }
    if (tid < 96) { float w = Wa1[tid]; sWa1d[tid] = pack2(w, w); }
    if (tid >= 96 && tid < 128) {
        int i = tid - 96;
        float w = bg1[i]; sbg1d[i] = pack2(w, w);
        sWg2[i] = Wg2[i];
    }
    if (tid < 16) {
        float w = ba1[tid]; sba1d[tid] = pack2(w, w);
        sWa2[tid] = Wa2[tid];
    }
    if (tid >= 16 && tid < 32) {
        int i = tid - 16;
        float2 pn = *(const float2*)&xy[((size_t)b * NPTS + n0 + i) * 2];
        syn[i] = pn.x; sxn[i] = pn.y;
        sdn[i] = g_d[b * NPTS + n0 + i];
    }
    if (tid >= 32 && tid < 96) {
        int i = tid - 32;
        float2 pm = *(const float2*)&xy[((size_t)b * NPTS + m0 + i) * 2];
        sym[i] = pm.x; sxm[i] = pm.y;
    }
    __syncthreads();

    int ty = tid >> 3;
    int tx = tid & 7;
    int n = n0 + ty;
    int mbase = m0 + tx * 8;

    float c0 = g_rot[2 * b], s0 = g_rot[2 * b + 1];
    float yn = syn[ty], xn = sxn[ty];

    const float sp = 1.41421356237f / 7.0f;
    const float gam = 1.0f / (2.0f * sp * sp + 1e-8f);
    const float C2 = 2.0f * gam * sp;
    const float cst1 = 0.60653065971f;
    const float cst2 = 0.13533528324f;
    const float cst3 = 0.011108996538f;
    const float cst4 = 3.3546262790e-4f;
    const float cst5 = 3.7266531720e-6f;
    const float cst6 = 1.5229979745e-8f;
    const float cst7 = 2.2897348457e-11f;

    ull f2[4][12];
    float c1s[8], s1s[8];
#pragma unroll
    for (int pp = 0; pp < 4; ++pp) {
        float t[2][12];
#pragma unroll
        for (int q = 0; q < 2; ++q) {
            int p = pp * 2 + q;
            float ym = sym[tx * 8 + p], xm = sxm[tx * 8 + p];
            float dy = yn - ym, dx = xn - xm;
            float r2 = dy * dy + dx * dx;
            float fr2 = r2 + 1e-8f;
            float r = sqrtf(fr2);
            float inv = rsqrtf(r2);
            float ct, st;
            if (r2 == 0.f) { ct = 1.f; st = 0.f; }
            else { ct = dx * inv; st = dy * inv; }
            float c1 = ct * c0 + st * s0;
            float s1 = st * c0 - ct * s0;
            c1s[p] = c1; s1s[p] = s1;
            t[q][0] = dy; t[q][1] = dx;
            float e0 = __expf(-gam * fr2);
            float Cr = __expf(C2 * r);
            t[q][2] = e0;
            float tt = e0;
            tt *= Cr; t[q][3] = tt * cst1;
            tt *= Cr; t[q][4] = tt * cst2;
            tt *= Cr; t[q][5] = tt * cst3;
            tt *= Cr; t[q][6] = tt * cst4;
            tt *= Cr; t[q][7] = tt * cst5;
            tt *= Cr; t[q][8] = tt * cst6;
            tt *= Cr; t[q][9] = tt * cst7;
            t[q][10] = c1; t[q][11] = s1;
        }
#pragma unroll
        for (int i = 0; i < 12; ++i) f2[pp][i] = pack2(t[0][i], t[1][i]);
    }

    float bg2v = bg2[0], ba2v = ba2[0];
    float accG[8], accA[8];
#pragma unroll
    for (int p = 0; p < 8; ++p) { accG[p] = bg2v; accA[p] = ba2v; }

#pragma unroll 4
    for (int j = 0; j < 32; ++j) {
        ull bj = sbg1d[j];
        ull h0 = bj, h1 = bj, h2 = bj, h3 = bj;
#pragma unroll
        for (int i = 0; i < 12; ++i) {
            ull w = sWg1d[i * 32 + j];
            h0 = fma2(f2[0][i], w, h0);
            h1 = fma2(f2[1][i], w, h1);
            h2 = fma2(f2[2][i], w, h2);
            h3 = fma2(f2[3][i], w, h3);
        }
        float a0, a1, a2, a3, a4, a5, a6, a7;
        unpack2(h0, a0, a1); unpack2(h1, a2, a3);
        unpack2(h2, a4, a5); unpack2(h3, a6, a7);
        float w2 = sWg2[j];
        accG[0] = fmaf(fmaxf(a0, 0.f), w2, accG[0]);
        accG[1] = fmaf(fmaxf(a1, 0.f), w2, accG[1]);
        accG[2] = fmaf(fmaxf(a2, 0.f), w2, accG[2]);
        accG[3] = fmaf(fmaxf(a3, 0.f), w2, accG[3]);
        accG[4] = fmaf(fmaxf(a4, 0.f), w2, accG[4]);
        accG[5] = fmaf(fmaxf(a5, 0.f), w2, accG[5]);
        accG[6] = fmaf(fmaxf(a6, 0.f), w2, accG[6]);
        accG[7] = fmaf(fmaxf(a7, 0.f), w2, accG[7]);
    }

    ull fa2[4][6];
#pragma unroll
    for (int pp = 0; pp < 4; ++pp) {
        float t[2][6];
#pragma unroll
        for (int q = 0; q < 2; ++q) {
            int p = pp * 2 + q;
            float c1 = c1s[p], s1 = s1s[p];
            float c2 = c1 * c1 - s1 * s1;
            float s2 = 2.f * c1 * s1;
            float c4 = c2 * c2 - s2 * s2;
            float s4 = 2.f * c2 * s2;
            t[q][0] = c1; t[q][1] = s1; t[q][2] = c2;
            t[q][3] = s2; t[q][4] = c4; t[q][5] = s4;
        }
#pragma unroll
        for (int i = 0; i < 6; ++i) fa2[pp][i] = pack2(t[0][i], t[1][i]);
    }

#pragma unroll 4
    for (int j = 0; j < 16; ++j) {
        ull bj = sba1d[j];
        ull h0 = bj, h1 = bj, h2 = bj, h3 = bj;
#pragma unroll
        for (int i = 0; i < 6; ++i) {
            ull w = sWa1d[i * 16 + j];
            h0 = fma2(fa2[0][i], w, h0);
            h1 = fma2(fa2[1][i], w, h1);
            h2 = fma2(fa2[2][i], w, h2);
            h3 = fma2(fa2[3][i], w, h3);
        }
        float a0, a1, a2, a3, a4, a5, a6, a7;
        unpack2(h0, a0, a1); unpack2(h1, a2, a3);
        unpack2(h2, a4, a5); unpack2(h3, a6, a7);
        float w2 = sWa2[j];
        accA[0] = fmaf(fmaxf(a0, 0.f), w2, accA[0]);
        accA[1] = fmaf(fmaxf(a1, 0.f), w2, accA[1]);
        accA[2] = fmaf(fmaxf(a2, 0.f), w2, accA[2]);
        accA[3] = fmaf(fmaxf(a3, 0.f), w2, accA[3]);
        accA[4] = fmaf(fmaxf(a4, 0.f), w2, accA[4]);
        accA[5] = fmaf(fmaxf(a5, 0.f), w2, accA[5]);
        accA[6] = fmaf(fmaxf(a6, 0.f), w2, accA[6]);
        accA[7] = fmaf(fmaxf(a7, 0.f), w2, accA[7]);
    }

    float ag = fmaxf(alpha_geom[0], 0.f);
    float aa = fmaxf(alpha_angle[0], 0.f);
    float ls = fmaxf(logit_scale[0], 0.01f);

    size_t off = ((size_t)b * NPTS + n) * NPTS + mbase;
    float4 u0 = *(const float4*)&g_S0[off];
    float4 v0 = *(const float4*)&g_S0[off + 4];
    float sv[8] = {u0.x, u0.y, u0.z, u0.w, v0.x, v0.y, v0.z, v0.w};
#pragma unroll
    for (int p = 0; p < 8; ++p) {
        float v = sv[p] + ag * accG[p] + aa * accA[p];
        if (n == mbase + p) v += sdn[ty];
        sv[p] = v * ls;
    }
    *(float4*)&S[off]     = make_float4(sv[0], sv[1], sv[2], sv[3]);
    *(float4*)&S[off + 4] = make_float4(sv[4], sv[5], sv[6], sv[7]);
}

// ---------------- launch ----------------
extern "C" void kernel_launch(void* const* d_in, const int* in_sizes, int n_in,
                              void* d_out, int out_size) {
    const float* feats       = (const float*)d_in[0];
    const float* xy          = (const float*)d_in[1];
    const float* Wq          = (const float*)d_in[2];
    const float* Wk          = (const float*)d_in[3];
    const float* Wpi         = (const float*)d_in[4];
    const float* bpi         = (const float*)d_in[5];
    const float* Wpj         = (const float*)d_in[6];
    const float* bpj         = (const float*)d_in[7];
    const float* alpha_pair  = (const float*)d_in[8];
    const float* Wg1         = (const float*)d_in[9];
    const float* bg1         = (const float*)d_in[10];
    const float* Wg2         = (const float*)d_in[11];
    const float* bg2         = (const float*)d_in[12];
    const float* alpha_geom  = (const float*)d_in[13];
    const float* Wa1         = (const float*)d_in[14];
    const float* ba1         = (const float*)d_in[15];
    const float* Wa2         = (const float*)d_in[16];
    const float* ba2         = (const float*)d_in[17];
    const float* alpha_angle = (const float*)d_in[18];
    const float* Wd          = (const float*)d_in[19];
    const float* bd          = (const float*)d_in[20];
    const float* logit_scale = (const float*)d_in[21];
    float* S = (float*)d_out;

    theta0_kernel<<<1, 256>>>(xy);
    fold_kernel<<<(NB * NPTS * (CDIM / 4) + 255) / 256, 256>>>(feats);
    pack_w_kernel<<<(CDIM * WPAD + 255) / 256, 256>>>(Wq, Wk, Wpi, Wpj, Wd);
    proj_mma_kernel<<<dim3(32, 7), 256>>>(bpi, bpj, alpha_pair, bd);
    qk_mma_kernel<<<dim3(8, 8, 8), 128>>>();
    pair_kernel<<<dim3(8, 32, 8), 128>>>(S, xy, Wg1, bg1, Wg2, bg2, alpha_geom,
                                         Wa1, ba1, Wa2, ba2, alpha_angle,
                                         logit_scale);
}

// round 17
// speedup vs baseline: 1.0402x; 1.0402x over previous
#include <cuda_runtime.h>

#define NPTS 512
#define CDIM 384
#define LDIM 208   // 192 QK + 16 pair
#define NB 8
#define WPAD 448   // padded packed-W width

typedef unsigned long long ull;

// ---------------- device scratch ----------------
__device__ float g_x[NB * NPTS * CDIM];      // folded features
__device__ float g_S0[NB * NPTS * NPTS];     // qk result (pre-epilogue)
__device__ float g_L[NB * NPTS * LDIM];      // [Q*HS | ap*relu(x@Wpi+bpi)]
__device__ float g_R[NB * NPTS * LDIM];      // [K    | relu(x@Wpj+bpj)   ]
__device__ float g_d[NB * NPTS];             // x@Wd + bd
__device__ float g_rot[2 * NB];              // (cos t0, sin t0) per batch
__device__ float g_W[CDIM * WPAD];           // packed+padded [Wq|Wk|Wpi|Wpj|Wd|0]

// ---------------- f32x2 helpers ----------------
__device__ __forceinline__ ull pack2(float lo, float hi) {
    ull r; asm("mov.b64 %0,{%1,%2};" : "=l"(r) : "f"(lo), "f"(hi)); return r;
}
__device__ __forceinline__ void unpack2(ull v, float& lo, float& hi) {
    asm("mov.b64 {%0,%1},%2;" : "=f"(lo), "=f"(hi) : "l"(v));
}
__device__ __forceinline__ ull fma2(ull a, ull b, ull c) {
    ull d; asm("fma.rn.f32x2 %0,%1,%2,%3;" : "=l"(d) : "l"(a), "l"(b), "l"(c)); return d;
}

// ---------------- tf32 mma helpers ----------------
__device__ __forceinline__ float f2tf32(float x) {
    unsigned u; asm("cvt.rna.tf32.f32 %0,%1;" : "=r"(u) : "f"(x));
    return __uint_as_float(u);
}
__device__ __forceinline__ void mma_tf32(float& c0, float& c1, float& c2, float& c3,
                                         unsigned a0, unsigned a1, unsigned a2, unsigned a3,
                                         unsigned b0, unsigned b1) {
    asm("mma.sync.aligned.m16n8k8.row.col.f32.tf32.tf32.f32 "
        "{%0,%1,%2,%3},{%4,%5,%6,%7},{%8,%9},{%0,%1,%2,%3};"
        : "+f"(c0), "+f"(c1), "+f"(c2), "+f"(c3)
        : "r"(a0), "r"(a1), "r"(a2), "r"(a3), "r"(b0), "r"(b1));
}

// ---------------- threefry / jax normal ----------------
__device__ __forceinline__ unsigned rotl32(unsigned v, int s) {
    return (v << s) | (v >> (32 - s));
}

__device__ void threefry2x32(unsigned k0, unsigned k1, unsigned c0, unsigned c1,
                             unsigned& o0, unsigned& o1) {
    unsigned k2 = k0 ^ k1 ^ 0x1BD11BDAu;
    unsigned x0 = c0 + k0, x1 = c1 + k1;
#define TF_R(r) { x0 += x1; x1 = rotl32(x1, r); x1 ^= x0; }
    TF_R(13) TF_R(15) TF_R(26) TF_R(6)   x0 += k1; x1 += k2 + 1u;
    TF_R(17) TF_R(29) TF_R(16) TF_R(24)  x0 += k2; x1 += k0 + 2u;
    TF_R(13) TF_R(15) TF_R(26) TF_R(6)   x0 += k0; x1 += k1 + 3u;
    TF_R(17) TF_R(29) TF_R(16) TF_R(24)  x0 += k1; x1 += k2 + 4u;
    TF_R(13) TF_R(15) TF_R(26) TF_R(6)   x0 += k2; x1 += k0 + 5u;
#undef TF_R
    o0 = x0; o1 = x1;
}

__device__ unsigned jax_random_bits_partitionable(unsigned i) {
    unsigned o0, o1;
    threefry2x32(0u, 42u, 0u, i, o0, o1);
    return o0 ^ o1;
}

__device__ float erfinv_f(float x) {
    float w = -log1pf(-x * x);
    float p;
    if (w < 5.0f) {
        w -= 2.5f;
        p = 2.81022636e-08f;
        p = fmaf(p, w, 3.43273939e-07f);
        p = fmaf(p, w, -3.5233877e-06f);
        p = fmaf(p, w, -4.39150654e-06f);
        p = fmaf(p, w, 0.00021858087f);
        p = fmaf(p, w, -0.00125372503f);
        p = fmaf(p, w, -0.00417768164f);
        p = fmaf(p, w, 0.246640727f);
        p = fmaf(p, w, 1.50140941f);
    } else {
        w = sqrtf(w) - 3.0f;
        p = -0.000200214257f;
        p = fmaf(p, w, 0.000100950558f);
        p = fmaf(p, w, 0.00134934322f);
        p = fmaf(p, w, -0.00367342844f);
        p = fmaf(p, w, 0.00573950773f);
        p = fmaf(p, w, -0.0076224613f);
        p = fmaf(p, w, 0.00943887047f);
        p = fmaf(p, w, 1.00167406f);
        p = fmaf(p, w, 2.83297682f);
    }
    return p * x;
}

__device__ float jax_normal_from_bits(unsigned bits) {
    float f = __uint_as_float((bits >> 9) | 0x3f800000u) - 1.0f;  // [0,1)
    float lo = __uint_as_float(0xBF7FFFFFu);                      // nextafter(-1,0)
    float span = 1.0f - lo;
    float val = f * span + lo;
    val = fmaxf(lo, val);
    return 1.41421356237f * erfinv_f(val);
}

// ---------------- theta0 ----------------
__global__ void theta0_kernel(const float* __restrict__ xy) {
    int w = threadIdx.x >> 5, lane = threadIdx.x & 31;
    const float* p = xy + (size_t)w * NPTS * 2;
    float sx = 0.f, sy = 0.f;
    for (int i = lane; i < NPTS; i += 32) { sx += p[2 * i]; sy += p[2 * i + 1]; }
    for (int o = 16; o; o >>= 1) {
        sx += __shfl_xor_sync(~0u, sx, o);
        sy += __shfl_xor_sync(~0u, sy, o);
    }
    float mx = sx / (float)NPTS, my = sy / (float)NPTS;
    float cxx = 0.f, cxy = 0.f, cyy = 0.f;
    for (int i = lane; i < NPTS; i += 32) {
        float a = p[2 * i] - mx, b = p[2 * i + 1] - my;
        cxx += a * a; cxy += a * b; cyy += b * b;
    }
    for (int o = 16; o; o >>= 1) {
        cxx += __shfl_xor_sync(~0u, cxx, o);
        cxy += __shfl_xor_sync(~0u, cxy, o);
        cyy += __shfl_xor_sync(~0u, cyy, o);
    }
    if (lane == 0) {
        float denom = (float)NPTS + 1e-8f;
        cxx /= denom; cxy /= denom; cyy /= denom;
        unsigned n0bits = jax_random_bits_partitionable(2u * (unsigned)w);
        unsigned n1bits = jax_random_bits_partitionable(2u * (unsigned)w + 1u);
        float v0 = jax_normal_from_bits(n0bits);
        float v1 = jax_normal_from_bits(n1bits);
        float nrm = sqrtf(v0 * v0 + v1 * v1);
        v0 /= (nrm + 1e-8f); v1 /= (nrm + 1e-8f);
#pragma unroll
        for (int it = 0; it < 5; ++it) {
            float w0 = cxx * v0 + cxy * v1;
            float w1 = cxy * v0 + cyy * v1;
            nrm = sqrtf(w0 * w0 + w1 * w1);
            v0 = w0 / (nrm + 1e-8f);
            v1 = w1 / (nrm + 1e-8f);
        }
        g_rot[2 * w] = v0;
        g_rot[2 * w + 1] = v1;
    }
}

// ---------------- fold feats -> g_x ----------------
__global__ void fold_kernel(const float* __restrict__ feats) {
    int idx = blockIdx.x * 256 + threadIdx.x;
    if (idx >= NB * NPTS * (CDIM / 4)) return;
    int c4 = idx % (CDIM / 4);
    int pn = idx / (CDIM / 4);
    int b = pn >> 9, n = pn & 511;
    const float* base = feats + ((size_t)b * (2 * NPTS + 1) + 1 + 2 * n) * CDIM + c4 * 4;
    float4 u = *(const float4*)base;
    float4 v = *(const float4*)(base + CDIM);
    float4 o = make_float4(0.5f * (u.x + v.x), 0.5f * (u.y + v.y),
                           0.5f * (u.z + v.z), 0.5f * (u.w + v.w));
    *(float4*)&g_x[(size_t)pn * CDIM + c4 * 4] = o;
}

// ---------------- pack projection weights ----------------
__global__ void pack_w_kernel(const float* __restrict__ Wq, const float* __restrict__ Wk,
                              const float* __restrict__ Wpi, const float* __restrict__ Wpj,
                              const float* __restrict__ Wd) {
    int idx = blockIdx.x * 256 + threadIdx.x;
    if (idx >= CDIM * WPAD) return;
    int k = idx / WPAD, j = idx - k * WPAD;
    float w;
    if (j < 192)       w = Wq[k * 192 + j];
    else if (j < 384)  w = Wk[k * 192 + j - 192];
    else if (j < 400)  w = Wpi[k * 16 + j - 384];
    else if (j < 416)  w = Wpj[k * 16 + j - 400];
    else if (j == 416) w = Wd[k];
    else               w = 0.f;
    g_W[idx] = w;
}

// ---------------- proj GEMM tf32 mma: 128x64, 256 thr, split-load pipeline ----------------
__global__ __launch_bounds__(256) void proj_mma_kernel(
    const float* __restrict__ bpi, const float* __restrict__ bpj,
    const float* __restrict__ alpha_pair, const float* __restrict__ bd) {
    __shared__ float As[2][128][20];
    __shared__ float Bs[2][64][20];
    int tid = threadIdx.x;
    int m0 = blockIdx.x * 128;     // point rows
    int n0c = blockIdx.y * 64;     // W cols
    int w = tid >> 5, lane = tid & 31;
    int wn = w >> 1, wm = w & 1;   // 4x2 warp grid: 32 rows x 32 cols each
    int g = lane >> 2, tc4 = lane & 3;

    float acc[2][4][4];
#pragma unroll
    for (int i = 0; i < 2; i++)
#pragma unroll
        for (int j = 0; j < 4; j++)
#pragma unroll
            for (int q = 0; q < 4; q++) acc[i][j][q] = 0.f;

    int frow = tid >> 1, fq = tid & 1;         // A fill: 128 rows, 8 floats each
    const float* xrow = g_x + (size_t)(m0 + frow) * CDIM;
    int wk = tid >> 4, wc4 = (tid & 15) * 4;   // B fill: 16 k x 16 col-quads

    float4 la0, la1, lb0;
#define PROJ_LDG(kc) { \
        la0 = *(const float4*)&xrow[(kc) + fq * 8]; \
        la1 = *(const float4*)&xrow[(kc) + fq * 8 + 4]; \
        lb0 = *(const float4*)&g_W[(size_t)((kc) + wk) * WPAD + n0c + wc4]; \
    }
#define PROJ_STS(buf) { \
        As[buf][frow][fq * 8 + 0] = f2tf32(la0.x); As[buf][frow][fq * 8 + 1] = f2tf32(la0.y); \
        As[buf][frow][fq * 8 + 2] = f2tf32(la0.z); As[buf][frow][fq * 8 + 3] = f2tf32(la0.w); \
        As[buf][frow][fq * 8 + 4] = f2tf32(la1.x); As[buf][frow][fq * 8 + 5] = f2tf32(la1.y); \
        As[buf][frow][fq * 8 + 6] = f2tf32(la1.z); As[buf][frow][fq * 8 + 7] = f2tf32(la1.w); \
        Bs[buf][wc4 + 0][wk] = f2tf32(lb0.x); Bs[buf][wc4 + 1][wk] = f2tf32(lb0.y); \
        Bs[buf][wc4 + 2][wk] = f2tf32(lb0.z); Bs[buf][wc4 + 3][wk] = f2tf32(lb0.w); \
    }

    PROJ_LDG(0);
    PROJ_STS(0);
    __syncthreads();

    const int NC = CDIM / 16;   // 24
    for (int c = 0; c < NC; ++c) {
        int cur = c & 1;
        if (c + 1 < NC) PROJ_LDG((c + 1) * 16);
#pragma unroll
        for (int kk = 0; kk < 16; kk += 8) {
            unsigned a[2][4];
#pragma unroll
            for (int i = 0; i < 2; i++) {
                int an = wn * 32 + i * 16;
                a[i][0] = __float_as_uint(As[cur][an + g][kk + tc4]);
                a[i][1] = __float_as_uint(As[cur][an + g + 8][kk + tc4]);
                a[i][2] = __float_as_uint(As[cur][an + g][kk + tc4 + 4]);
                a[i][3] = __float_as_uint(As[cur][an + g + 8][kk + tc4 + 4]);
            }
            unsigned bb[4][2];
#pragma unroll
            for (int j = 0; j < 4; j++) {
                int bm = wm * 32 + j * 8;
                bb[j][0] = __float_as_uint(Bs[cur][bm + g][kk + tc4]);
                bb[j][1] = __float_as_uint(Bs[cur][bm + g][kk + tc4 + 4]);
            }
#pragma unroll
            for (int i = 0; i < 2; i++)
#pragma unroll
                for (int j = 0; j < 4; j++)
                    mma_tf32(acc[i][j][0], acc[i][j][1], acc[i][j][2], acc[i][j][3],
                             a[i][0], a[i][1], a[i][2], a[i][3], bb[j][0], bb[j][1]);
        }
        if (c + 1 < NC) PROJ_STS(cur ^ 1);
        __syncthreads();
    }
#undef PROJ_LDG
#undef PROJ_STS

    float ap = fmaxf(alpha_pair[0], 0.f);
    float bd0 = bd[0];
    const float HS = 0.17677669529663687f;  // 1/sqrt(32)

#pragma unroll
    for (int i = 0; i < 2; i++) {
#pragma unroll
        for (int j = 0; j < 4; j++) {
#pragma unroll
            for (int q = 0; q < 4; q++) {
                int p = m0 + wn * 32 + i * 16 + g + (q >= 2 ? 8 : 0);
                int col = n0c + wm * 32 + j * 8 + tc4 * 2 + (q & 1);
                float val = acc[i][j][q];
                if (col < 192)       g_L[(size_t)p * LDIM + col] = val * HS;
                else if (col < 384)  g_R[(size_t)p * LDIM + (col - 192)] = val;
                else if (col < 400)  g_L[(size_t)p * LDIM + 192 + (col - 384)] = fmaxf(val + bpi[col - 384], 0.f) * ap;
                else if (col < 416)  g_R[(size_t)p * LDIM + 192 + (col - 400)] = fmaxf(val + bpj[col - 400], 0.f);
                else if (col == 416) g_d[p] = val + bd0;
            }
        }
    }
}

// ---------------- qk GEMM tf32 mma: 64x64 tile, 128 thr, split-load pipeline ----------------
__global__ __launch_bounds__(128) void qk_mma_kernel() {
    __shared__ float Ls[2][64][20];
    __shared__ float Rs[2][64][20];
    int tid = threadIdx.x;
    int b = blockIdx.z;
    int m0 = blockIdx.x * 64;
    int n0 = blockIdx.y * 64;
    int w = tid >> 5, lane = tid & 31;
    int wn = w >> 1, wm = w & 1;
    int g = lane >> 2, tc4 = lane & 3;

    float acc[2][4][4];
#pragma unroll
    for (int i = 0; i < 2; i++)
#pragma unroll
        for (int j = 0; j < 4; j++)
#pragma unroll
            for (int q = 0; q < 4; q++) acc[i][j][q] = 0.f;

    int frow = tid >> 1, fq = tid & 1;
    const float* lrow = g_L + (size_t)(b * NPTS + n0 + frow) * LDIM;
    const float* rrow = g_R + (size_t)(b * NPTS + m0 + frow) * LDIM;

    float4 ll0, ll1, rr0, rr1;
#define QK_LDG(kc) { \
        ll0 = *(const float4*)&lrow[(kc) + fq * 8]; \
        ll1 = *(const float4*)&lrow[(kc) + fq * 8 + 4]; \
        rr0 = *(const float4*)&rrow[(kc) + fq * 8]; \
        rr1 = *(const float4*)&rrow[(kc) + fq * 8 + 4]; \
    }
#define QK_STS(buf) { \
        Ls[buf][frow][fq * 8 + 0] = f2tf32(ll0.x); Ls[buf][frow][fq * 8 + 1] = f2tf32(ll0.y); \
        Ls[buf][frow][fq * 8 + 2] = f2tf32(ll0.z); Ls[buf][frow][fq * 8 + 3] = f2tf32(ll0.w); \
        Ls[buf][frow][fq * 8 + 4] = f2tf32(ll1.x); Ls[buf][frow][fq * 8 + 5] = f2tf32(ll1.y); \
        Ls[buf][frow][fq * 8 + 6] = f2tf32(ll1.z); Ls[buf][frow][fq * 8 + 7] = f2tf32(ll1.w); \
        Rs[buf][frow][fq * 8 + 0] = f2tf32(rr0.x); Rs[buf][frow][fq * 8 + 1] = f2tf32(rr0.y); \
        Rs[buf][frow][fq * 8 + 2] = f2tf32(rr0.z); Rs[buf][frow][fq * 8 + 3] = f2tf32(rr0.w); \
        Rs[buf][frow][fq * 8 + 4] = f2tf32(rr1.x); Rs[buf][frow][fq * 8 + 5] = f2tf32(rr1.y); \
        Rs[buf][frow][fq * 8 + 6] = f2tf32(rr1.z); Rs[buf][frow][fq * 8 + 7] = f2tf32(rr1.w); \
    }

    QK_LDG(0);
    QK_STS(0);
    __syncthreads();

    const int NC = LDIM / 16;   // 13
    for (int c = 0; c < NC; ++c) {
        int cur = c & 1;
        if (c + 1 < NC) QK_LDG((c + 1) * 16);
#pragma unroll
        for (int kk = 0; kk < 16; kk += 8) {
            unsigned a[2][4];
#pragma unroll
            for (int i = 0; i < 2; i++) {
                int an = wn * 32 + i * 16;
                a[i][0] = __float_as_uint(Ls[cur][an + g][kk + tc4]);
                a[i][1] = __float_as_uint(Ls[cur][an + g + 8][kk + tc4]);
                a[i][2] = __float_as_uint(Ls[cur][an + g][kk + tc4 + 4]);
                a[i][3] = __float_as_uint(Ls[cur][an + g + 8][kk + tc4 + 4]);
            }
            unsigned bb[4][2];
#pragma unroll
            for (int j = 0; j < 4; j++) {
                int bm = wm * 32 + j * 8;
                bb[j][0] = __float_as_uint(Rs[cur][bm + g][kk + tc4]);
                bb[j][1] = __float_as_uint(Rs[cur][bm + g][kk + tc4 + 4]);
            }
#pragma unroll
            for (int i = 0; i < 2; i++)
#pragma unroll
                for (int j = 0; j < 4; j++)
                    mma_tf32(acc[i][j][0], acc[i][j][1], acc[i][j][2], acc[i][j][3],
                             a[i][0], a[i][1], a[i][2], a[i][3], bb[j][0], bb[j][1]);
        }
        if (c + 1 < NC) QK_STS(cur ^ 1);
        __syncthreads();
    }
#undef QK_LDG
#undef QK_STS

#pragma unroll
    for (int i = 0; i < 2; i++) {
#pragma unroll
        for (int j = 0; j < 4; j++) {
            int rn = n0 + wn * 32 + i * 16 + g;
            int cm = m0 + wm * 32 + j * 8 + tc4 * 2;
            size_t o0 = ((size_t)b * NPTS + rn) * NPTS + cm;
            size_t o1 = o0 + 8 * NPTS;
            *(float2*)&g_S0[o0] = make_float2(acc[i][j][0], acc[i][j][1]);
            *(float2*)&g_S0[o1] = make_float2(acc[i][j][2], acc[i][j][3]);
        }
    }
}

// ---------------- per-pair MLP epilogue: 128 thr, 16n x 64m, 8 m/thread ----------------
__global__ __launch_bounds__(128) void pair_kernel(
    float* __restrict__ S, const float* __restrict__ xy,
    const float* __restrict__ Wg1, const float* __restrict__ bg1,
    const float* __restrict__ Wg2, const float* __restrict__ bg2,
    const float* __restrict__ alpha_geom,
    const float* __restrict__ Wa1, const float* __restrict__ ba1,
    const float* __restrict__ Wa2, const float* __restrict__ ba2,
    const float* __restrict__ alpha_angle,
    const float* __restrict__ logit_scale) {
    __shared__ ull sWg1d[12 * 32];
    __shared__ ull sbg1d[32];
    __shared__ float sWg2[32];
    __shared__ ull sWa1d[6 * 16];
    __shared__ ull sba1d[16];
    __shared__ float sWa2[16];
    __shared__ float sxn[16], syn[16], sdn[16];
    __shared__ float sxm[64], sym[64];

    int tid = threadIdx.x;
    int b = blockIdx.z;
    int m0 = blockIdx.x * 64;
    int n0 = blockIdx.y * 16;

    for (int i = tid; i < 384; i += 128) { float w = Wg1[i]; sWg1d[i] = pack2(w, w); }
    if (tid < 96) { float w = Wa1[tid]; sWa1d[tid] = pack2(w, w); }
    if (tid >= 96 && tid < 128) {
        int i = tid - 96;
        float w = bg1[i]; sbg1d[i] = pack2(w, w);
        sWg2[i] = Wg2[i];
    }
    if (tid < 16) {
        float w = ba1[tid]; sba1d[tid] = pack2(w, w);
        sWa2[tid] = Wa2[tid];
    }
    if (tid >= 16 && tid < 32) {
        int i = tid - 16;
        float2 pn = *(const float2*)&xy[((size_t)b * NPTS + n0 + i) * 2];
        syn[i] = pn.x; sxn[i] = pn.y;
        sdn[i] = g_d[b * NPTS + n0 + i];
    }
    if (tid >= 32 && tid < 96) {
        int i = tid - 32;
        float2 pm = *(const float2*)&xy[((size_t)b * NPTS + m0 + i) * 2];
        sym[i] = pm.x; sxm[i] = pm.y;
    }
    __syncthreads();

    int ty = tid >> 3;
    int tx = tid & 7;
    int n = n0 + ty;
    int mbase = m0 + tx * 8;

    float c0 = g_rot[2 * b], s0 = g_rot[2 * b + 1];
    float yn = syn[ty], xn = sxn[ty];

    const float sp = 1.41421356237f / 7.0f;
    const float gam = 1.0f / (2.0f * sp * sp + 1e-8f);
    const float C2 = 2.0f * gam * sp;
    const float cst1 = 0.60653065971f;
    const float cst2 = 0.13533528324f;
    const float cst3 = 0.011108996538f;
    const float cst4 = 3.3546262790e-4f;
    const float cst5 = 3.7266531720e-6f;
    const float cst6 = 1.5229979745e-8f;
    const float cst7 = 2.2897348457e-11f;

    ull f2[4][12];
    float c1s[8], s1s[8];
#pragma unroll
    for (int pp = 0; pp < 4; ++pp) {
        float t[2][12];
#pragma unroll
        for (int q = 0; q < 2; ++q) {
            int p = pp * 2 + q;
            float ym = sym[tx * 8 + p], xm = sxm[tx * 8 + p];
            float dy = yn - ym, dx = xn - xm;
            float r2 = dy * dy + dx * dx;
            float fr2 = r2 + 1e-8f;
            float r = sqrtf(fr2);
            float inv = rsqrtf(r2);
            float ct, st;
            if (r2 == 0.f) { ct = 1.f; st = 0.f; }
            else { ct = dx * inv; st = dy * inv; }
            float c1 = ct * c0 + st * s0;
            float s1 = st * c0 - ct * s0;
            c1s[p] = c1; s1s[p] = s1;
            t[q][0] = dy; t[q][1] = dx;
            float e0 = __expf(-gam * fr2);
            float Cr = __expf(C2 * r);
            t[q][2] = e0;
            float tt = e0;
            tt *= Cr; t[q][3] = tt * cst1;
            tt *= Cr; t[q][4] = tt * cst2;
            tt *= Cr; t[q][5] = tt * cst3;
            tt *= Cr; t[q][6] = tt * cst4;
            tt *= Cr; t[q][7] = tt * cst5;
            tt *= Cr; t[q][8] = tt * cst6;
            tt *= Cr; t[q][9] = tt * cst7;
            t[q][10] = c1; t[q][11] = s1;
        }
#pragma unroll
        for (int i = 0; i < 12; ++i) f2[pp][i] = pack2(t[0][i], t[1][i]);
    }

    float bg2v = bg2[0], ba2v = ba2[0];
    float accG[8], accA[8];
#pragma unroll
    for (int p = 0; p < 8; ++p) { accG[p] = bg2v; accA[p] = ba2v; }

#pragma unroll 4
    for (int j = 0; j < 32; ++j) {
        ull bj = sbg1d[j];
        ull h0 = bj, h1 = bj, h2 = bj, h3 = bj;
#pragma unroll
        for (int i = 0; i < 12; ++i) {
            ull w = sWg1d[i * 32 + j];
            h0 = fma2(f2[0][i], w, h0);
            h1 = fma2(f2[1][i], w, h1);
            h2 = fma2(f2[2][i], w, h2);
            h3 = fma2(f2[3][i], w, h3);
        }
        float a0, a1, a2, a3, a4, a5, a6, a7;
        unpack2(h0, a0, a1); unpack2(h1, a2, a3);
        unpack2(h2, a4, a5); unpack2(h3, a6, a7);
        float w2 = sWg2[j];
        accG[0] = fmaf(fmaxf(a0, 0.f), w2, accG[0]);
        accG[1] = fmaf(fmaxf(a1, 0.f), w2, accG[1]);
        accG[2] = fmaf(fmaxf(a2, 0.f), w2, accG[2]);
        accG[3] = fmaf(fmaxf(a3, 0.f), w2, accG[3]);
        accG[4] = fmaf(fmaxf(a4, 0.f), w2, accG[4]);
        accG[5] = fmaf(fmaxf(a5, 0.f), w2, accG[5]);
        accG[6] = fmaf(fmaxf(a6, 0.f), w2, accG[6]);
        accG[7] = fmaf(fmaxf(a7, 0.f), w2, accG[7]);
    }

    ull fa2[4][6];
#pragma unroll
    for (int pp = 0; pp < 4; ++pp) {
        float t[2][6];
#pragma unroll
        for (int q = 0; q < 2; ++q) {
            int p = pp * 2 + q;
            float c1 = c1s[p], s1 = s1s[p];
            float c2 = c1 * c1 - s1 * s1;
            float s2 = 2.f * c1 * s1;
            float c4 = c2 * c2 - s2 * s2;
            float s4 = 2.f * c2 * s2;
            t[q][0] = c1; t[q][1] = s1; t[q][2] = c2;
            t[q][3] = s2; t[q][4] = c4; t[q][5] = s4;
        }
#pragma unroll
        for (int i = 0; i < 6; ++i) fa2[pp][i] = pack2(t[0][i], t[1][i]);
    }

#pragma unroll 4
    for (int j = 0; j < 16; ++j) {
        ull bj = sba1d[j];
        ull h0 = bj, h1 = bj, h2 = bj, h3 = bj;
#pragma unroll
        for (int i = 0; i < 6; ++i) {
            ull w = sWa1d[i * 16 + j];
            h0 = fma2(fa2[0][i], w, h0);
            h1 = fma2(fa2[1][i], w, h1);
            h2 = fma2(fa2[2][i], w, h2);
            h3 = fma2(fa2[3][i], w, h3);
        }
        float a0, a1, a2, a3, a4, a5, a6, a7;
        unpack2(h0, a0, a1); unpack2(h1, a2, a3);
        unpack2(h2, a4, a5); unpack2(h3, a6, a7);
        float w2 = sWa2[j];
        accA[0] = fmaf(fmaxf(a0, 0.f), w2, accA[0]);
        accA[1] = fmaf(fmaxf(a1, 0.f), w2, accA[1]);
        accA[2] = fmaf(fmaxf(a2, 0.f), w2, accA[2]);
        accA[3] = fmaf(fmaxf(a3, 0.f), w2, accA[3]);
        accA[4] = fmaf(fmaxf(a4, 0.f), w2, accA[4]);
        accA[5] = fmaf(fmaxf(a5, 0.f), w2, accA[5]);
        accA[6] = fmaf(fmaxf(a6, 0.f), w2, accA[6]);
        accA[7] = fmaf(fmaxf(a7, 0.f), w2, accA[7]);
    }

    float ag = fmaxf(alpha_geom[0], 0.f);
    float aa = fmaxf(alpha_angle[0], 0.f);
    float ls = fmaxf(logit_scale[0], 0.01f);

    size_t off = ((size_t)b * NPTS + n) * NPTS + mbase;
    float4 u0 = *(const float4*)&g_S0[off];
    float4 v0 = *(const float4*)&g_S0[off + 4];
    float sv[8] = {u0.x, u0.y, u0.z, u0.w, v0.x, v0.y, v0.z, v0.w};
#pragma unroll
    for (int p = 0; p < 8; ++p) {
        float v = sv[p] + ag * accG[p] + aa * accA[p];
        if (n == mbase + p) v += sdn[ty];
        sv[p] = v * ls;
    }
    *(float4*)&S[off]     = make_float4(sv[0], sv[1], sv[2], sv[3]);
    *(float4*)&S[off + 4] = make_float4(sv[4], sv[5], sv[6], sv[7]);
}

// ---------------- launch ----------------
extern "C" void kernel_launch(void* const* d_in, const int* in_sizes, int n_in,
                              void* d_out, int out_size) {
    const float* feats       = (const float*)d_in[0];
    const float* xy          = (const float*)d_in[1];
    const float* Wq          = (const float*)d_in[2];
    const float* Wk          = (const float*)d_in[3];
    const float* Wpi         = (const float*)d_in[4];
    const float* bpi         = (const float*)d_in[5];
    const float* Wpj         = (const float*)d_in[6];
    const float* bpj         = (const float*)d_in[7];
    const float* alpha_pair  = (const float*)d_in[8];
    const float* Wg1         = (const float*)d_in[9];
    const float* bg1         = (const float*)d_in[10];
    const float* Wg2         = (const float*)d_in[11];
    const float* bg2         = (const float*)d_in[12];
    const float* alpha_geom  = (const float*)d_in[13];
    const float* Wa1         = (const float*)d_in[14];
    const float* ba1         = (const float*)d_in[15];
    const float* Wa2         = (const float*)d_in[16];
    const float* ba2         = (const float*)d_in[17];
    const float* alpha_angle = (const float*)d_in[18];
    const float* Wd          = (const float*)d_in[19];
    const float* bd          = (const float*)d_in[20];
    const float* logit_scale = (const float*)d_in[21];
    float* S = (float*)d_out;

    theta0_kernel<<<1, 256>>>(xy);
    fold_kernel<<<(NB * NPTS * (CDIM / 4) + 255) / 256, 256>>>(feats);
    pack_w_kernel<<<(CDIM * WPAD + 255) / 256, 256>>>(Wq, Wk, Wpi, Wpj, Wd);
    proj_mma_kernel<<<dim3(32, 7), 256>>>(bpi, bpj, alpha_pair, bd);
    qk_mma_kernel<<<dim3(8, 8, 8), 128>>>();
    pair_kernel<<<dim3(8, 32, 8), 128>>>(S, xy, Wg1, bg1, Wg2, bg2, alpha_geom,
                                         Wa1, ba1, Wa2, ba2, alpha_angle,
                                         logit_scale);
}